// round 1
// baseline (speedup 1.0000x reference)
#include <cuda_runtime.h>
#include <cuda_bf16.h>
#include <cstdint>

// Problem constants (fixed shape: path_fea [131072, 64, 1, 1, 2] fp32)
#define GNUM 8192     // groups = B / 16
#define PNUM 16       // samples per group
#define DNUM 128      // feature dim = 64*2
#define NTILE 64      // GNUM / 128
#define LDB 136       // smem row stride in bf16 elems (128 + 8 pad)

// -------- device scratch (no allocs allowed) --------
__device__ __nv_bfloat16 g_centerB[GNUM * DNUM];   // bf16 centers for Gram
__device__ float g_sq[GNUM];                       // fp32 ||c||^2
__device__ float g_inter_acc;
__device__ float g_intra_acc;

__global__ void zero_acc_kernel() {
    g_inter_acc = 0.0f;
    g_intra_acc = 0.0f;
}

// ============================================================
// Kernel A: per-group center + ||c||^2 + intra hinge (fused, memory-bound)
// One block (512 threads) per group.
// ============================================================
__global__ void __launch_bounds__(512) center_intra_kernel(const float* __restrict__ fea) {
    __shared__ float sf[PNUM * DNUM];   // 2048 floats = 8KB, layout [s][d]
    __shared__ float sc[DNUM];
    __shared__ float s_red[4];
    __shared__ float s_h[PNUM];

    const int g = blockIdx.x;
    const int tid = threadIdx.x;
    const float* base = fea + (size_t)g * (PNUM * DNUM);

    // cooperative coalesced load: 2048 floats / 512 threads = 4 each
    #pragma unroll
    for (int i = 0; i < 4; i++)
        sf[tid + i * 512] = base[tid + i * 512];
    __syncthreads();

    // center: threads 0..127 each own one dim
    float c = 0.0f;
    if (tid < DNUM) {
        #pragma unroll
        for (int s = 0; s < PNUM; s++) c += sf[s * DNUM + tid];
        c *= (1.0f / PNUM);
        sc[tid] = c;
        g_centerB[(size_t)g * DNUM + tid] = __float2bfloat16(c);
    }
    // ||c||^2 in fp32: warp-reduce over the 4 dim-warps
    float cs = (tid < DNUM) ? c * c : 0.0f;
    #pragma unroll
    for (int o = 16; o > 0; o >>= 1) cs += __shfl_down_sync(0xffffffffu, cs, o);
    if (tid < DNUM && (tid & 31) == 0) s_red[tid >> 5] = cs;
    __syncthreads();
    if (tid == 0) g_sq[g] = s_red[0] + s_red[1] + s_red[2] + s_red[3];

    // intra: warp w handles sample w (16 warps)
    const int w = tid >> 5, l = tid & 31;
    float acc = 0.0f;
    #pragma unroll
    for (int q = 0; q < 4; q++) {
        int dd = l + 32 * q;
        float df = sf[w * DNUM + dd] - sc[dd];
        acc += df * df;
    }
    #pragma unroll
    for (int o = 16; o > 0; o >>= 1) acc += __shfl_down_sync(0xffffffffu, acc, o);
    if (l == 0) {
        float d = sqrtf(acc) - 0.1f;
        d = fmaxf(d, 0.0f);
        s_h[w] = d * d;
    }
    __syncthreads();
    if (tid == 0) {
        float t = 0.0f;
        #pragma unroll
        for (int s = 0; s < PNUM; s++) t += s_h[s];
        atomicAdd(&g_intra_acc, t);
    }
}

// ============================================================
// Kernel B: bf16 tensor-core SYRK over centers + inter hinge epilogue.
// 2080 triangular 128x128 tiles, 256 threads/CTA, K=128 in one smem stage.
// ============================================================
__device__ __forceinline__ void ldm_x4(uint32_t (&r)[4], const __nv_bfloat16* p) {
    uint32_t addr = (uint32_t)__cvta_generic_to_shared(p);
    asm volatile("ldmatrix.sync.aligned.m8n8.x4.shared.b16 {%0,%1,%2,%3}, [%4];"
        : "=r"(r[0]), "=r"(r[1]), "=r"(r[2]), "=r"(r[3]) : "r"(addr));
}

__device__ __forceinline__ void mma_bf16(float (&d)[4], const uint32_t (&a)[4],
                                         uint32_t b0, uint32_t b1) {
    asm volatile(
        "mma.sync.aligned.m16n8k16.row.col.f32.bf16.bf16.f32 "
        "{%0,%1,%2,%3}, {%4,%5,%6,%7}, {%8,%9}, {%0,%1,%2,%3};"
        : "+f"(d[0]), "+f"(d[1]), "+f"(d[2]), "+f"(d[3])
        : "r"(a[0]), "r"(a[1]), "r"(a[2]), "r"(a[3]), "r"(b0), "r"(b1));
}

__global__ void __launch_bounds__(256) gram_inter_kernel() {
    extern __shared__ __nv_bfloat16 sm[];
    __nv_bfloat16* sA = sm;                 // [128][LDB]
    __nv_bfloat16* sB = sm + 128 * LDB;     // [128][LDB]
    __shared__ float sqA[128], sqB[128];
    __shared__ float s_red[8];

    const int tid = threadIdx.x;

    // map linear block id -> upper-triangular tile (ti <= tj)
    int idx = blockIdx.x;
    int ti = 0;
    int rem = NTILE;
    while (idx >= rem) { idx -= rem; rem--; ti++; }
    const int tj = ti + idx;
    const int i0 = ti * 128, j0 = tj * 128;

    // stage both 128x128 bf16 tiles (uint4 = 8 bf16; 16 per row)
    const uint4* gc = (const uint4*)g_centerB;
    for (int k = tid; k < 2048; k += 256) {
        int r = k >> 4, c = k & 15;
        uint4 va = gc[(size_t)(i0 + r) * 16 + c];
        *(uint4*)&sA[r * LDB + c * 8] = va;
        uint4 vb = gc[(size_t)(j0 + r) * 16 + c];
        *(uint4*)&sB[r * LDB + c * 8] = vb;
    }
    if (tid < 128) { sqA[tid] = g_sq[i0 + tid]; sqB[tid] = g_sq[j0 + tid]; }
    __syncthreads();

    const int wid = tid >> 5, lane = tid & 31;
    const int wm = wid & 1;     // 2 warps along M: rows 64*wm
    const int wn = wid >> 1;    // 4 warps along N: cols 32*wn
    const int lrow = lane & 15;
    const int lcol = (lane >> 4) << 3;  // 0 or 8

    float acc[4][4][4];
    #pragma unroll
    for (int mt = 0; mt < 4; mt++)
        #pragma unroll
        for (int nt = 0; nt < 4; nt++)
            #pragma unroll
            for (int r = 0; r < 4; r++) acc[mt][nt][r] = 0.0f;

    #pragma unroll
    for (int ks = 0; ks < 8; ks++) {
        const int kb = ks * 16;
        uint32_t a[4][4];
        #pragma unroll
        for (int mt = 0; mt < 4; mt++)
            ldm_x4(a[mt], &sA[(64 * wm + 16 * mt + lrow) * LDB + kb + lcol]);
        uint32_t b[2][4];
        #pragma unroll
        for (int nh = 0; nh < 2; nh++)
            ldm_x4(b[nh], &sB[(32 * wn + 16 * nh + lrow) * LDB + kb + lcol]);

        #pragma unroll
        for (int mt = 0; mt < 4; mt++) {
            #pragma unroll
            for (int nt = 0; nt < 4; nt++) {
                const int nh = nt >> 1;
                const int sel = nt & 1;
                // ldmatrix x4 on B region: r0=n0-7/k0-7, r1=n8-15/k0-7,
                //                          r2=n0-7/k8-15, r3=n8-15/k8-15
                uint32_t b0 = b[nh][sel ? 1 : 0];
                uint32_t b1 = b[nh][sel ? 3 : 2];
                mma_bf16(acc[mt][nt], a[mt], b0, b1);
            }
        }
    }

    // epilogue: d^2 = ||ci||^2 + ||cj||^2 - 2*gram, hinge at margin 1.0, i<j only
    const int r_l = lane >> 2;           // 0..7
    const int c_l = 2 * (lane & 3);      // 0,2,4,6
    float lsum = 0.0f;
    #pragma unroll
    for (int mt = 0; mt < 4; mt++) {
        const int mi = 64 * wm + 16 * mt;
        #pragma unroll
        for (int nt = 0; nt < 4; nt++) {
            const int nj = 32 * wn + 8 * nt;
            #pragma unroll
            for (int rr = 0; rr < 2; rr++) {
                #pragma unroll
                for (int cc = 0; cc < 2; cc++) {
                    int li = mi + r_l + 8 * rr;      // local row in tile
                    int lj = nj + c_l + cc;          // local col in tile
                    int gi = i0 + li, gj = j0 + lj;
                    if (gi < gj) {
                        float d2 = sqA[li] + sqB[lj] - 2.0f * acc[mt][nt][rr * 2 + cc];
                        if (d2 < 1.0f) {             // rare: hinge active
                            float d = sqrtf(fmaxf(d2, 0.0f));
                            float h = 1.0f - d;
                            lsum += h * h;
                        }
                    }
                }
            }
        }
    }

    // block reduce + one atomic per CTA
    #pragma unroll
    for (int o = 16; o > 0; o >>= 1) lsum += __shfl_down_sync(0xffffffffu, lsum, o);
    if (lane == 0) s_red[wid] = lsum;
    __syncthreads();
    if (tid == 0) {
        float t = 0.0f;
        #pragma unroll
        for (int w = 0; w < 8; w++) t += s_red[w];
        atomicAdd(&g_inter_acc, t);
    }
}

__global__ void finalize_kernel(float* __restrict__ out) {
    // n_pairs = G*(G-1)/2 = 8192*8191/2
    out[0] = g_inter_acc / 33550336.0f;
    out[1] = g_intra_acc / (float)(GNUM * PNUM);
}

extern "C" void kernel_launch(void* const* d_in, const int* in_sizes, int n_in,
                              void* d_out, int out_size) {
    const float* fea = (const float*)d_in[0];
    float* out = (float*)d_out;

    zero_acc_kernel<<<1, 1>>>();
    center_intra_kernel<<<GNUM, 512>>>(fea);

    const int smem_bytes = 2 * 128 * LDB * (int)sizeof(__nv_bfloat16);  // 69632
    cudaFuncSetAttribute(gram_inter_kernel,
                         cudaFuncAttributeMaxDynamicSharedMemorySize, smem_bytes);
    gram_inter_kernel<<<NTILE * (NTILE + 1) / 2, 256, smem_bytes>>>();

    finalize_kernel<<<1, 1>>>(out);
}

// round 3
// speedup vs baseline: 1.0026x; 1.0026x over previous
#include <cuda_runtime.h>
#include <cuda_bf16.h>
#include <cstdint>

// Problem constants (fixed shape: path_fea [131072, 64, 1, 1, 2] fp32)
#define GNUM 8192        // groups = B / 16
#define PNUM 16          // samples per group
#define DNUM 128         // feature dim
#define NTILE 64         // GNUM / 128
#define NTILES_TRI 2080  // 64*65/2 triangular 128x128 tiles
#define GRID_B 296       // persistent CTAs (148 SMs * 2)
#define LDB 136          // smem row stride in bf16 (128 + 8 pad)

// -------- device scratch (no allocs allowed) --------
__device__ __nv_bfloat16 g_centerB[GNUM * DNUM];
__device__ float g_sq[GNUM];
__device__ float g_intra_part[GNUM];
__device__ float g_inter_part[GRID_B];
__device__ unsigned int g_done = 0;   // self-resetting

// ===================== helpers =====================
__device__ __forceinline__ uint32_t smem_u32(const void* p) {
    uint32_t a;
    asm("{ .reg .u64 t; cvta.to.shared.u64 t, %1; cvt.u32.u64 %0, t; }"
        : "=r"(a) : "l"(p));
    return a;
}
__device__ __forceinline__ void cp16(uint32_t dst, const void* src) {
    asm volatile("cp.async.cg.shared.global [%0], [%1], 16;"
                 :: "r"(dst), "l"(src) : "memory");
}
__device__ __forceinline__ void cp_commit() {
    asm volatile("cp.async.commit_group;" ::: "memory");
}
__device__ __forceinline__ void cp_wait0() {
    asm volatile("cp.async.wait_group 0;" ::: "memory");
}
__device__ __forceinline__ void ldm_x4(uint32_t (&r)[4], const __nv_bfloat16* p) {
    uint32_t addr = smem_u32(p);
    asm volatile("ldmatrix.sync.aligned.m8n8.x4.shared.b16 {%0,%1,%2,%3}, [%4];"
        : "=r"(r[0]), "=r"(r[1]), "=r"(r[2]), "=r"(r[3]) : "r"(addr));
}
__device__ __forceinline__ void mma_bf16(float (&d)[4], const uint32_t (&a)[4],
                                         uint32_t b0, uint32_t b1) {
    asm volatile(
        "mma.sync.aligned.m16n8k16.row.col.f32.bf16.bf16.f32 "
        "{%0,%1,%2,%3}, {%4,%5,%6,%7}, {%8,%9}, {%0,%1,%2,%3};"
        : "+f"(d[0]), "+f"(d[1]), "+f"(d[2]), "+f"(d[3])
        : "r"(a[0]), "r"(a[1]), "r"(a[2]), "r"(a[3]), "r"(b0), "r"(b1));
}

// ============================================================
// Kernel A: per-group center + ||c||^2 + intra hinge (memory-bound)
// ============================================================
__global__ void __launch_bounds__(512) center_intra_kernel(const float* __restrict__ fea) {
    __shared__ float sf[PNUM * DNUM];
    __shared__ float sc[DNUM];
    __shared__ float s_red[4];
    __shared__ float s_h[PNUM];

    const int g = blockIdx.x;
    const int tid = threadIdx.x;
    const float* base = fea + (size_t)g * (PNUM * DNUM);

    #pragma unroll
    for (int i = 0; i < 4; i++)
        sf[tid + i * 512] = base[tid + i * 512];
    __syncthreads();

    float c = 0.0f;
    if (tid < DNUM) {
        #pragma unroll
        for (int s = 0; s < PNUM; s++) c += sf[s * DNUM + tid];
        c *= (1.0f / PNUM);
        sc[tid] = c;
        g_centerB[(size_t)g * DNUM + tid] = __float2bfloat16(c);
    }
    float cs = (tid < DNUM) ? c * c : 0.0f;
    #pragma unroll
    for (int o = 16; o > 0; o >>= 1) cs += __shfl_down_sync(0xffffffffu, cs, o);
    if (tid < DNUM && (tid & 31) == 0) s_red[tid >> 5] = cs;
    __syncthreads();
    if (tid == 0) g_sq[g] = s_red[0] + s_red[1] + s_red[2] + s_red[3];

    const int w = tid >> 5, l = tid & 31;
    float acc = 0.0f;
    #pragma unroll
    for (int q = 0; q < 4; q++) {
        int dd = l + 32 * q;
        float df = sf[w * DNUM + dd] - sc[dd];
        acc += df * df;
    }
    #pragma unroll
    for (int o = 16; o > 0; o >>= 1) acc += __shfl_down_sync(0xffffffffu, acc, o);
    if (l == 0) {
        float d = fmaxf(sqrtf(acc) - 0.1f, 0.0f);
        s_h[w] = d * d;
    }
    __syncthreads();
    if (tid == 0) {
        float t = 0.0f;
        #pragma unroll
        for (int s = 0; s < PNUM; s++) t += s_h[s];
        g_intra_part[g] = t;
    }
}

// ============================================================
// Kernel B: persistent HMMA SYRK (128x128 tiles), cp.async-pipelined B,
// register epilogue hinge, fused finalize (last CTA).
// smem: sA [128][LDB] + sB[2][128][LDB] bf16
// ============================================================
__global__ void __launch_bounds__(256, 2) gram_finalize_kernel(float* __restrict__ out) {
    extern __shared__ __nv_bfloat16 sm[];
    __nv_bfloat16* sA = sm;                          // 34816 B
    __nv_bfloat16* sBs[2] = { sm + 128 * LDB, sm + 2 * 128 * LDB };

    __shared__ float s_red[8];
    __shared__ unsigned s_last;

    const int tid = threadIdx.x;
    const int wid = tid >> 5, lane = tid & 31;

    // chunk of triangular tiles for this CTA
    const int t0 = (int)(((long long)blockIdx.x * NTILES_TRI) / gridDim.x);
    const int t1 = (int)(((long long)(blockIdx.x + 1) * NTILES_TRI) / gridDim.x);

    int ti = 0, rowoff = 0;
    while (t0 >= rowoff + (NTILE - ti)) { rowoff += NTILE - ti; ti++; }
    int tj = ti + (t0 - rowoff);

    const char* gcb = (const char*)g_centerB;
    // per-thread staging coords: 8 chunks of 16B each
    const int srow0 = tid >> 4;          // rows srow0 + 16*i
    const int sc16 = (tid & 15) * 16;    // byte column within 256B row

    const int wm = wid & 1;
    const int wn = wid >> 1;
    const int lrow = lane & 15;
    const int lcol = (lane >> 4) << 3;
    const int r_l = lane >> 2;
    const int c_l = 2 * (lane & 3);

    float lsum = 0.0f;
    int cur_ti = -1;
    int stage = 0;
    bool pref = false;

    for (int t = t0; t < t1; t++) {
        const int i0 = ti * 128, j0 = tj * 128;

        if (!pref) {
            __syncthreads();  // previous compute done before overwriting buffers
            if (ti != cur_ti) {
                #pragma unroll
                for (int i = 0; i < 8; i++) {
                    int r = srow0 + 16 * i;
                    cp16(smem_u32((char*)sA + r * (LDB * 2) + sc16),
                         gcb + ((size_t)(i0 + r) * 256 + sc16));
                }
                cur_ti = ti;
            }
            #pragma unroll
            for (int i = 0; i < 8; i++) {
                int r = srow0 + 16 * i;
                cp16(smem_u32((char*)sBs[stage] + r * (LDB * 2) + sc16),
                     gcb + ((size_t)(j0 + r) * 256 + sc16));
            }
            cp_commit();
            cp_wait0();
            __syncthreads();
        } else {
            cp_wait0();
            __syncthreads();
        }

        // next-tile coords; prefetch next B if same row (A stays valid)
        int nti = ti, ntj = tj + 1;
        if (ntj == NTILE) { nti = ti + 1; ntj = nti; }
        const bool canpref = (t + 1 < t1) && (nti == ti);
        if (canpref) {
            #pragma unroll
            for (int i = 0; i < 8; i++) {
                int r = srow0 + 16 * i;
                cp16(smem_u32((char*)sBs[stage ^ 1] + r * (LDB * 2) + sc16),
                     gcb + ((size_t)(ntj * 128 + r) * 256 + sc16));
            }
            cp_commit();
        }

        // ---- compute 128x128 tile ----
        const __nv_bfloat16* sB = sBs[stage];
        float acc[4][4][4];
        #pragma unroll
        for (int mt = 0; mt < 4; mt++)
            #pragma unroll
            for (int nt = 0; nt < 4; nt++)
                #pragma unroll
                for (int r = 0; r < 4; r++) acc[mt][nt][r] = 0.0f;

        #pragma unroll
        for (int ks = 0; ks < 8; ks++) {
            const int kb = ks * 16;
            uint32_t a[4][4];
            #pragma unroll
            for (int mt = 0; mt < 4; mt++)
                ldm_x4(a[mt], &sA[(64 * wm + 16 * mt + lrow) * LDB + kb + lcol]);
            uint32_t b[2][4];
            #pragma unroll
            for (int nh = 0; nh < 2; nh++)
                ldm_x4(b[nh], &sB[(32 * wn + 16 * nh + lrow) * LDB + kb + lcol]);

            #pragma unroll
            for (int mt = 0; mt < 4; mt++) {
                #pragma unroll
                for (int nt = 0; nt < 4; nt++) {
                    const int nh = nt >> 1;
                    const int sel = nt & 1;
                    mma_bf16(acc[mt][nt], a[mt], b[nh][sel ? 1 : 0], b[nh][sel ? 3 : 2]);
                }
            }
        }

        // ---- epilogue: hinge on d^2 directly from registers ----
        #pragma unroll
        for (int mt = 0; mt < 4; mt++) {
            const int mi = 64 * wm + 16 * mt;
            #pragma unroll
            for (int rr = 0; rr < 2; rr++) {
                const int gi = i0 + mi + r_l + 8 * rr;
                const float qa = __ldg(&g_sq[gi]);
                #pragma unroll
                for (int nt = 0; nt < 4; nt++) {
                    const int nj = 32 * wn + 8 * nt;
                    #pragma unroll
                    for (int cc = 0; cc < 2; cc++) {
                        const int gj = j0 + nj + c_l + cc;
                        if (gi < gj) {
                            float d2 = qa + __ldg(&g_sq[gj])
                                       - 2.0f * acc[mt][nt][rr * 2 + cc];
                            if (d2 < 1.0f) {            // hinge active: ~never
                                float d = sqrtf(fmaxf(d2, 0.0f));
                                float h = 1.0f - d;
                                lsum += h * h;
                            }
                        }
                    }
                }
            }
        }

        if (canpref) { stage ^= 1; pref = true; } else { pref = false; }
        ti = nti; tj = ntj;
    }

    // per-CTA inter reduction
    #pragma unroll
    for (int o = 16; o > 0; o >>= 1) lsum += __shfl_down_sync(0xffffffffu, lsum, o);
    if (lane == 0) s_red[wid] = lsum;
    __syncthreads();
    if (tid == 0) {
        float tsum = 0.0f;
        #pragma unroll
        for (int w = 0; w < 8; w++) tsum += s_red[w];
        g_inter_part[blockIdx.x] = tsum;
    }

    // last-CTA-done finalize
    __threadfence();
    __syncthreads();
    if (tid == 0) {
        unsigned v = atomicAdd(&g_done, 1u);
        s_last = (v == gridDim.x - 1) ? 1u : 0u;
    }
    __syncthreads();
    if (s_last) {
        __threadfence();
        float a = 0.0f, b = 0.0f;
        for (int i = tid; i < GRID_B; i += 256) a += g_inter_part[i];
        for (int i = tid; i < GNUM; i += 256) b += g_intra_part[i];
        #pragma unroll
        for (int o = 16; o > 0; o >>= 1) {
            a += __shfl_down_sync(0xffffffffu, a, o);
            b += __shfl_down_sync(0xffffffffu, b, o);
        }
        __shared__ float fa[8], fb[8];
        if (lane == 0) { fa[wid] = a; fb[wid] = b; }
        __syncthreads();
        if (tid == 0) {
            float A = 0.0f, B = 0.0f;
            #pragma unroll
            for (int w = 0; w < 8; w++) { A += fa[w]; B += fb[w]; }
            out[0] = A / 33550336.0f;              // G*(G-1)/2
            out[1] = B / (float)(GNUM * PNUM);
            g_done = 0;                            // reset for next replay
        }
    }
}

extern "C" void kernel_launch(void* const* d_in, const int* in_sizes, int n_in,
                              void* d_out, int out_size) {
    const float* fea = (const float*)d_in[0];
    float* out = (float*)d_out;

    center_intra_kernel<<<GNUM, 512>>>(fea);

    const int smem_bytes = 3 * 128 * LDB * (int)sizeof(__nv_bfloat16);  // 104448
    cudaFuncSetAttribute(gram_finalize_kernel,
                         cudaFuncAttributeMaxDynamicSharedMemorySize, smem_bytes);
    gram_finalize_kernel<<<GRID_B, 256, smem_bytes>>>(out);
}

// round 4
// speedup vs baseline: 1.1686x; 1.1656x over previous
#include <cuda_runtime.h>
#include <cuda_bf16.h>
#include <cuda_fp8.h>
#include <cstdint>

// Problem constants (fixed shape: path_fea [131072, 64, 1, 1, 2] fp32)
#define GNUM 8192        // groups = B / 16
#define PNUM 16          // samples per group
#define DNUM 128         // feature dim
#define NTILE 64         // GNUM / 128
#define NTILES_TRI 2080  // 64*65/2 triangular 128x128 tiles
#define GRID_B 296       // persistent CTAs (148 SMs * 2)
#define TROW 144         // smem tile row stride in bytes (128 fp8 + 16 pad)

// -------- device scratch (no allocs allowed) --------
__device__ uint8_t g_centerF8[GNUM * DNUM];   // e4m3 centers (k-major, 128B/row)
__device__ float g_sq[GNUM];                  // fp32 ||c||^2
__device__ float g_intra_part[GNUM];
__device__ float g_inter_part[GRID_B];
__device__ unsigned int g_done = 0;           // self-resetting

// ===================== helpers =====================
__device__ __forceinline__ uint32_t smem_u32(const void* p) {
    uint32_t a;
    asm("{ .reg .u64 t; cvta.to.shared.u64 t, %1; cvt.u32.u64 %0, t; }"
        : "=r"(a) : "l"(p));
    return a;
}
__device__ __forceinline__ void cp16(uint32_t dst, const void* src) {
    asm volatile("cp.async.cg.shared.global [%0], [%1], 16;"
                 :: "r"(dst), "l"(src) : "memory");
}
__device__ __forceinline__ void cp_commit() {
    asm volatile("cp.async.commit_group;" ::: "memory");
}
__device__ __forceinline__ void cp_wait0() {
    asm volatile("cp.async.wait_group 0;" ::: "memory");
}
__device__ __forceinline__ void ldm_x4(uint32_t (&r)[4], const void* p) {
    uint32_t addr = smem_u32(p);
    asm volatile("ldmatrix.sync.aligned.m8n8.x4.shared.b16 {%0,%1,%2,%3}, [%4];"
        : "=r"(r[0]), "=r"(r[1]), "=r"(r[2]), "=r"(r[3]) : "r"(addr));
}
// FP8 e4m3 MMA: D(f32) += A(16x32 e4m3) * B^T(8x32 e4m3)
__device__ __forceinline__ void mma_fp8(float (&d)[4], const uint32_t (&a)[4],
                                        uint32_t b0, uint32_t b1) {
    asm volatile(
        "mma.sync.aligned.m16n8k32.row.col.f32.e4m3.e4m3.f32 "
        "{%0,%1,%2,%3}, {%4,%5,%6,%7}, {%8,%9}, {%0,%1,%2,%3};"
        : "+f"(d[0]), "+f"(d[1]), "+f"(d[2]), "+f"(d[3])
        : "r"(a[0]), "r"(a[1]), "r"(a[2]), "r"(a[3]), "r"(b0), "r"(b1));
}

// ============================================================
// Kernel A: per-group center + ||c||^2 + intra hinge (memory-bound)
// ============================================================
__global__ void __launch_bounds__(512) center_intra_kernel(const float* __restrict__ fea) {
    __shared__ float sf[PNUM * DNUM];
    __shared__ float sc[DNUM];
    __shared__ float s_red[4];
    __shared__ float s_h[PNUM];

    const int g = blockIdx.x;
    const int tid = threadIdx.x;

    // one float4 per thread: 512 * 16B = 8KB group
    const float4* base4 = (const float4*)(fea + (size_t)g * (PNUM * DNUM));
    ((float4*)sf)[tid] = base4[tid];
    __syncthreads();

    float c = 0.0f;
    if (tid < DNUM) {
        #pragma unroll
        for (int s = 0; s < PNUM; s++) c += sf[s * DNUM + tid];
        c *= (1.0f / PNUM);
        sc[tid] = c;
        g_centerF8[(size_t)g * DNUM + tid] =
            (uint8_t)__nv_cvt_float_to_fp8(c, __NV_SATFINITE, __NV_E4M3);
    }
    float cs = (tid < DNUM) ? c * c : 0.0f;
    #pragma unroll
    for (int o = 16; o > 0; o >>= 1) cs += __shfl_down_sync(0xffffffffu, cs, o);
    if (tid < DNUM && (tid & 31) == 0) s_red[tid >> 5] = cs;
    __syncthreads();
    if (tid == 0) g_sq[g] = s_red[0] + s_red[1] + s_red[2] + s_red[3];

    const int w = tid >> 5, l = tid & 31;
    float acc = 0.0f;
    #pragma unroll
    for (int q = 0; q < 4; q++) {
        int dd = l + 32 * q;
        float df = sf[w * DNUM + dd] - sc[dd];
        acc += df * df;
    }
    #pragma unroll
    for (int o = 16; o > 0; o >>= 1) acc += __shfl_down_sync(0xffffffffu, acc, o);
    if (l == 0) {
        float d = fmaxf(sqrtf(acc) - 0.1f, 0.0f);
        s_h[w] = d * d;
    }
    __syncthreads();
    if (tid == 0) {
        float t = 0.0f;
        #pragma unroll
        for (int s = 0; s < PNUM; s++) t += s_h[s];
        g_intra_part[g] = t;
    }
}

// ============================================================
// Kernel B: persistent FP8 QMMA SYRK (128x128 tiles), double-buffered
// A and B via cp.async, register hinge epilogue, fused finalize.
// smem: 4 tiles of 128 rows x TROW bytes (A0,A1,B0,B1) = 73728 B
// ============================================================
__global__ void __launch_bounds__(256, 2) gram_finalize_kernel(float* __restrict__ out) {
    extern __shared__ uint8_t sm[];
    uint8_t* tile[4] = { sm, sm + 128 * TROW, sm + 2 * 128 * TROW, sm + 3 * 128 * TROW };
    // tile[0..1] = A buffers, tile[2..3] = B buffers

    __shared__ float s_red[8];
    __shared__ unsigned s_last;

    const int tid = threadIdx.x;
    const int wid = tid >> 5, lane = tid & 31;

    const int t0 = (int)(((long long)blockIdx.x * NTILES_TRI) / gridDim.x);
    const int t1 = (int)(((long long)(blockIdx.x + 1) * NTILES_TRI) / gridDim.x);

    int ti = 0, rowoff = 0;
    while (t0 >= rowoff + (NTILE - ti)) { rowoff += NTILE - ti; ti++; }
    int tj = ti + (t0 - rowoff);

    const uint8_t* gcb = g_centerF8;

    // staging: 1024 chunks of 16B per 16KB tile; thread handles 4
    auto load_tile = [&](uint8_t* dst, int g0) {
        #pragma unroll
        for (int i = 0; i < 4; i++) {
            int u = tid + 256 * i;
            int r = u >> 3, c16 = (u & 7) * 16;
            cp16(smem_u32(dst + r * TROW + c16),
                 gcb + (size_t)(g0 + r) * 128 + c16);
        }
    };

    const int wm = wid & 1;            // 2 warps along M (64 rows each)
    const int wn = wid >> 1;           // 4 warps along N (32 cols each)
    const int lrow = lane & 15;
    const int lcolB = ((lane >> 4) << 3) * 2;  // byte offset: 0 or 16
    const int r_l = lane >> 2;
    const int c_l = 2 * (lane & 3);

    int aSt = 0, bSt = 2;

    // prologue loads
    load_tile(tile[aSt], ti * 128);
    load_tile(tile[bSt], tj * 128);
    cp_commit();

    float lsum = 0.0f;

    for (int t = t0; t < t1; t++) {
        const int i0 = ti * 128, j0 = tj * 128;
        cp_wait0();
        __syncthreads();

        // prefetch next tile into alternate buffers
        int nti = ti, ntj = tj + 1;
        if (ntj == NTILE) { nti = ti + 1; ntj = nti; }
        const bool havenext = (t + 1 < t1);
        const bool newrow = (nti != ti);
        if (havenext) {
            if (newrow) load_tile(tile[aSt ^ 1], nti * 128);
            load_tile(tile[bSt ^ 1], ntj * 128);
            cp_commit();
        }

        // ---- compute 128x128 tile (FP8, 4 k-steps of k32) ----
        const uint8_t* sA = tile[aSt];
        const uint8_t* sB = tile[bSt];
        float acc[4][4][4];
        #pragma unroll
        for (int mt = 0; mt < 4; mt++)
            #pragma unroll
            for (int nt = 0; nt < 4; nt++)
                #pragma unroll
                for (int r = 0; r < 4; r++) acc[mt][nt][r] = 0.0f;

        #pragma unroll
        for (int ks = 0; ks < 4; ks++) {
            const int kb = ks * 32;   // byte offset of k-slice
            uint32_t a[4][4];
            #pragma unroll
            for (int mt = 0; mt < 4; mt++)
                ldm_x4(a[mt], sA + (64 * wm + 16 * mt + lrow) * TROW + kb + lcolB);
            uint32_t b[2][4];
            #pragma unroll
            for (int nh = 0; nh < 2; nh++)
                ldm_x4(b[nh], sB + (32 * wn + 16 * nh + lrow) * TROW + kb + lcolB);

            #pragma unroll
            for (int mt = 0; mt < 4; mt++) {
                #pragma unroll
                for (int nt = 0; nt < 4; nt++) {
                    const int nh = nt >> 1;
                    const int sel = nt & 1;
                    mma_fp8(acc[mt][nt], a[mt], b[nh][sel ? 1 : 0], b[nh][sel ? 3 : 2]);
                }
            }
        }

        // ---- epilogue: hinge on d^2 from registers ----
        float qa[8], qb[8];
        #pragma unroll
        for (int mt = 0; mt < 4; mt++) {
            qa[2 * mt]     = __ldg(&g_sq[i0 + 64 * wm + 16 * mt + r_l]);
            qa[2 * mt + 1] = __ldg(&g_sq[i0 + 64 * wm + 16 * mt + r_l + 8]);
        }
        #pragma unroll
        for (int nt = 0; nt < 4; nt++) {
            qb[2 * nt]     = __ldg(&g_sq[j0 + 32 * wn + 8 * nt + c_l]);
            qb[2 * nt + 1] = __ldg(&g_sq[j0 + 32 * wn + 8 * nt + c_l + 1]);
        }
        const bool diag = (ti == tj);
        #pragma unroll
        for (int mt = 0; mt < 4; mt++) {
            #pragma unroll
            for (int rr = 0; rr < 2; rr++) {
                const int li = 64 * wm + 16 * mt + r_l + 8 * rr;
                const float qav = qa[2 * mt + rr];
                #pragma unroll
                for (int nt = 0; nt < 4; nt++) {
                    #pragma unroll
                    for (int cc = 0; cc < 2; cc++) {
                        const int lj = 32 * wn + 8 * nt + c_l + cc;
                        float d2 = qav + qb[2 * nt + cc]
                                   - 2.0f * acc[mt][nt][rr * 2 + cc];
                        bool valid = diag ? (li < lj) : true;
                        if (valid && d2 < 1.0f) {       // hinge active: ~never
                            float d = sqrtf(fmaxf(d2, 0.0f));
                            float h = 1.0f - d;
                            lsum += h * h;
                        }
                    }
                }
            }
        }

        if (havenext) {
            if (newrow) aSt ^= 1;
            bSt ^= 1;
            ti = nti; tj = ntj;
        }
    }

    // per-CTA inter reduction
    #pragma unroll
    for (int o = 16; o > 0; o >>= 1) lsum += __shfl_down_sync(0xffffffffu, lsum, o);
    if (lane == 0) s_red[wid] = lsum;
    __syncthreads();
    if (tid == 0) {
        float tsum = 0.0f;
        #pragma unroll
        for (int w = 0; w < 8; w++) tsum += s_red[w];
        g_inter_part[blockIdx.x] = tsum;
    }

    // last-CTA-done finalize
    __threadfence();
    __syncthreads();
    if (tid == 0) {
        unsigned v = atomicAdd(&g_done, 1u);
        s_last = (v == gridDim.x - 1) ? 1u : 0u;
    }
    __syncthreads();
    if (s_last) {
        __threadfence();
        float a = 0.0f, b = 0.0f;
        for (int i = tid; i < GRID_B; i += 256) a += g_inter_part[i];
        for (int i = tid; i < GNUM; i += 256) b += g_intra_part[i];
        #pragma unroll
        for (int o = 16; o > 0; o >>= 1) {
            a += __shfl_down_sync(0xffffffffu, a, o);
            b += __shfl_down_sync(0xffffffffu, b, o);
        }
        __shared__ float fa[8], fb[8];
        if (lane == 0) { fa[wid] = a; fb[wid] = b; }
        __syncthreads();
        if (tid == 0) {
            float A = 0.0f, B = 0.0f;
            #pragma unroll
            for (int w = 0; w < 8; w++) { A += fa[w]; B += fb[w]; }
            out[0] = A / 33550336.0f;              // G*(G-1)/2
            out[1] = B / (float)(GNUM * PNUM);
            g_done = 0;                            // reset for next replay
        }
    }
}

extern "C" void kernel_launch(void* const* d_in, const int* in_sizes, int n_in,
                              void* d_out, int out_size) {
    const float* fea = (const float*)d_in[0];
    float* out = (float*)d_out;

    center_intra_kernel<<<GNUM, 512>>>(fea);

    const int smem_bytes = 4 * 128 * TROW;   // 73728
    cudaFuncSetAttribute(gram_finalize_kernel,
                         cudaFuncAttributeMaxDynamicSharedMemorySize, smem_bytes);
    gram_finalize_kernel<<<GRID_B, 256, smem_bytes>>>(out);
}

// round 8
// speedup vs baseline: 1.4415x; 1.2335x over previous
#include <cuda_runtime.h>
#include <cuda_bf16.h>
#include <cuda_fp16.h>
#include <cuda_fp8.h>
#include <cstdint>

// Problem constants (fixed shape: path_fea [131072, 64, 1, 1, 2] fp32)
#define GNUM 8192        // groups = B / 16
#define PNUM 16          // samples per group
#define DNUM 128         // feature dim
#define NTILE 64         // GNUM / 128
#define NTILES_TRI 2080  // 64*65/2 triangular 128x128 tiles
#define GRID_B 444       // persistent CTAs (148 SMs * 3)
#define TROW 144         // smem tile row stride in bytes (128 fp8 + 16 pad)

// -------- device scratch (no allocs allowed) --------
__device__ uint8_t g_centerF8[GNUM * DNUM];   // e4m3 centers (k-major, 128B/row)
__device__ float g_sq[GNUM];                  // fp32 ||c||^2
__device__ float g_intra_part[GNUM];
__device__ float g_inter_part[GRID_B];
__device__ unsigned int g_done = 0;           // self-resetting

// ===================== helpers =====================
__device__ __forceinline__ uint32_t smem_u32(const void* p) {
    uint32_t a;
    asm("{ .reg .u64 t; cvta.to.shared.u64 t, %1; cvt.u32.u64 %0, t; }"
        : "=r"(a) : "l"(p));
    return a;
}
__device__ __forceinline__ void cp16(uint32_t dst, const void* src) {
    asm volatile("cp.async.cg.shared.global [%0], [%1], 16;"
                 :: "r"(dst), "l"(src) : "memory");
}
__device__ __forceinline__ void cp_commit() {
    asm volatile("cp.async.commit_group;" ::: "memory");
}
__device__ __forceinline__ void cp_wait0() {
    asm volatile("cp.async.wait_group 0;" ::: "memory");
}
__device__ __forceinline__ void ldm_x4(uint32_t (&r)[4], const void* p) {
    uint32_t addr = smem_u32(p);
    asm volatile("ldmatrix.sync.aligned.m8n8.x4.shared.b16 {%0,%1,%2,%3}, [%4];"
        : "=r"(r[0]), "=r"(r[1]), "=r"(r[2]), "=r"(r[3]) : "r"(addr));
}
// FP8 e4m3 MMA with f16 accumulators: D(f16) += A(16x32 e4m3) * B^T(8x32 e4m3)
__device__ __forceinline__ void mma_fp8_h(uint32_t (&d)[2], const uint32_t (&a)[4],
                                          uint32_t b0, uint32_t b1) {
    asm volatile(
        "mma.sync.aligned.m16n8k32.row.col.f16.e4m3.e4m3.f16 "
        "{%0,%1}, {%2,%3,%4,%5}, {%6,%7}, {%0,%1};"
        : "+r"(d[0]), "+r"(d[1])
        : "r"(a[0]), "r"(a[1]), "r"(a[2]), "r"(a[3]), "r"(b0), "r"(b1));
}

// ============================================================
// Kernel A: per-group center + ||c||^2 + intra hinge (memory-bound)
// ============================================================
__global__ void __launch_bounds__(512) center_intra_kernel(const float* __restrict__ fea) {
    __shared__ float sf[PNUM * DNUM];
    __shared__ float sc[DNUM];
    __shared__ float s_red[4];
    __shared__ float s_h[PNUM];

    const int g = blockIdx.x;
    const int tid = threadIdx.x;

    const float4* base4 = (const float4*)(fea + (size_t)g * (PNUM * DNUM));
    ((float4*)sf)[tid] = base4[tid];
    __syncthreads();

    float c = 0.0f;
    if (tid < DNUM) {
        #pragma unroll
        for (int s = 0; s < PNUM; s++) c += sf[s * DNUM + tid];
        c *= (1.0f / PNUM);
        sc[tid] = c;
        g_centerF8[(size_t)g * DNUM + tid] =
            (uint8_t)__nv_cvt_float_to_fp8(c, __NV_SATFINITE, __NV_E4M3);
    }
    float cs = (tid < DNUM) ? c * c : 0.0f;
    #pragma unroll
    for (int o = 16; o > 0; o >>= 1) cs += __shfl_down_sync(0xffffffffu, cs, o);
    if (tid < DNUM && (tid & 31) == 0) s_red[tid >> 5] = cs;
    __syncthreads();
    if (tid == 0) g_sq[g] = s_red[0] + s_red[1] + s_red[2] + s_red[3];

    const int w = tid >> 5, l = tid & 31;
    float acc = 0.0f;
    #pragma unroll
    for (int q = 0; q < 4; q++) {
        int dd = l + 32 * q;
        float df = sf[w * DNUM + dd] - sc[dd];
        acc += df * df;
    }
    #pragma unroll
    for (int o = 16; o > 0; o >>= 1) acc += __shfl_down_sync(0xffffffffu, acc, o);
    if (l == 0) {
        float d = fmaxf(sqrtf(acc) - 0.1f, 0.0f);
        s_h[w] = d * d;
    }
    __syncthreads();
    if (tid == 0) {
        float t = 0.0f;
        #pragma unroll
        for (int s = 0; s < PNUM; s++) t += s_h[s];
        g_intra_part[g] = t;
    }
}

// ============================================================
// Kernel B: persistent FP8 QMMA SYRK (128x128 tiles, f16 accum),
// double-buffered cp.async tiles, max-screened hinge epilogue,
// fused finalize (last CTA).
// ============================================================
__global__ void __launch_bounds__(256, 3) gram_finalize_kernel(float* __restrict__ out) {
    extern __shared__ uint8_t sm[];
    uint8_t* tile[4] = { sm, sm + 128 * TROW, sm + 2 * 128 * TROW, sm + 3 * 128 * TROW };

    __shared__ float s_red[8];
    __shared__ float s_gmin;
    __shared__ unsigned s_last;

    const int tid = threadIdx.x;
    const int wid = tid >> 5, lane = tid & 31;

    const int t0 = (int)(((long long)blockIdx.x * NTILES_TRI) / gridDim.x);
    const int t1 = (int)(((long long)(blockIdx.x + 1) * NTILES_TRI) / gridDim.x);

    int ti = 0, rowoff = 0;
    while (t0 >= rowoff + (NTILE - ti)) { rowoff += NTILE - ti; ti++; }
    int tj = ti + (t0 - rowoff);

    const uint8_t* gcb = g_centerF8;

    auto load_tile = [&](uint8_t* dst, int g0) {
        #pragma unroll
        for (int i = 0; i < 4; i++) {
            int u = tid + 256 * i;
            int r = u >> 3, c16 = (u & 7) * 16;
            cp16(smem_u32(dst + r * TROW + c16),
                 gcb + (size_t)(g0 + r) * 128 + c16);
        }
    };

    const int wm = wid & 1;
    const int wn = wid >> 1;
    const int lrow = lane & 15;
    const int lcolB = ((lane >> 4) << 3) * 2;
    const int r_l = lane >> 2;
    const int c_l = 2 * (lane & 3);

    int aSt = 0, bSt = 2;

    // prologue tile loads (overlap with gmin scan below)
    load_tile(tile[aSt], ti * 128);
    load_tile(tile[bSt], tj * 128);
    cp_commit();

    // global min of ||c||^2 (for the no-hinge screen)
    {
        float m = 3.4e38f;
        for (int i = tid; i < GNUM; i += 256) m = fminf(m, g_sq[i]);
        #pragma unroll
        for (int o = 16; o > 0; o >>= 1)
            m = fminf(m, __shfl_xor_sync(0xffffffffu, m, o));
        if (lane == 0) s_red[wid] = m;
        __syncthreads();
        if (tid == 0) {
            float mm = s_red[0];
            #pragma unroll
            for (int w = 1; w < 8; w++) mm = fminf(mm, s_red[w]);
            s_gmin = mm;
        }
        __syncthreads();
    }
    const float screen = s_gmin - 0.5f;   // no hinge anywhere if maxg <= screen

    float lsum = 0.0f;

    for (int t = t0; t < t1; t++) {
        const int i0 = ti * 128, j0 = tj * 128;
        cp_wait0();
        __syncthreads();

        int nti = ti, ntj = tj + 1;
        if (ntj == NTILE) { nti = ti + 1; ntj = nti; }
        const bool havenext = (t + 1 < t1);
        const bool newrow = (nti != ti);
        if (havenext) {
            if (newrow) load_tile(tile[aSt ^ 1], nti * 128);
            load_tile(tile[bSt ^ 1], ntj * 128);
            cp_commit();
        }

        // ---- compute 128x128 tile (FP8 -> f16 accum, 4 k-steps of k32) ----
        const uint8_t* sA = tile[aSt];
        const uint8_t* sB = tile[bSt];
        uint32_t acc[4][4][2];
        #pragma unroll
        for (int mt = 0; mt < 4; mt++)
            #pragma unroll
            for (int nt = 0; nt < 4; nt++) {
                acc[mt][nt][0] = 0u; acc[mt][nt][1] = 0u;
            }

        #pragma unroll
        for (int ks = 0; ks < 4; ks++) {
            const int kb = ks * 32;
            uint32_t a[4][4];
            #pragma unroll
            for (int mt = 0; mt < 4; mt++)
                ldm_x4(a[mt], sA + (64 * wm + 16 * mt + lrow) * TROW + kb + lcolB);
            uint32_t b[2][4];
            #pragma unroll
            for (int nh = 0; nh < 2; nh++)
                ldm_x4(b[nh], sB + (32 * wn + 16 * nh + lrow) * TROW + kb + lcolB);

            #pragma unroll
            for (int mt = 0; mt < 4; mt++) {
                #pragma unroll
                for (int nt = 0; nt < 4; nt++) {
                    const int nh = nt >> 1;
                    const int sel = nt & 1;
                    mma_fp8_h(acc[mt][nt], a[mt], b[nh][sel ? 1 : 0], b[nh][sel ? 3 : 2]);
                }
            }
        }

        // ---- epilogue: packed-max screen, exact path only if needed ----
        const bool diag = (ti == tj);
        __half2 m2 = __float2half2_rn(-60000.0f);
        #pragma unroll
        for (int mt = 0; mt < 4; mt++)
            #pragma unroll
            for (int nt = 0; nt < 4; nt++) {
                m2 = __hmax2(m2, *(const __half2*)&acc[mt][nt][0]);
                m2 = __hmax2(m2, *(const __half2*)&acc[mt][nt][1]);
            }
        float maxg = fmaxf(__low2float(m2), __high2float(m2));

        if (diag || maxg > screen) {
            // exact (rare / diagonal tiles only)
            #pragma unroll
            for (int mt = 0; mt < 4; mt++) {
                const int li0 = 64 * wm + 16 * mt + r_l;
                const float qa0 = __ldg(&g_sq[i0 + li0]);
                const float qa1 = __ldg(&g_sq[i0 + li0 + 8]);
                #pragma unroll
                for (int nt = 0; nt < 4; nt++) {
                    const int lj0 = 32 * wn + 8 * nt + c_l;
                    const float qb0 = __ldg(&g_sq[j0 + lj0]);
                    const float qb1 = __ldg(&g_sq[j0 + lj0 + 1]);
                    float2 v0 = __half22float2(*(const __half2*)&acc[mt][nt][0]);
                    float2 v1 = __half22float2(*(const __half2*)&acc[mt][nt][1]);
                    const float gv[4] = { v0.x, v0.y, v1.x, v1.y };
                    const float qav[4] = { qa0, qa0, qa1, qa1 };
                    const float qbv[4] = { qb0, qb1, qb0, qb1 };
                    const int liv[4] = { li0, li0, li0 + 8, li0 + 8 };
                    const int ljv[4] = { lj0, lj0 + 1, lj0, lj0 + 1 };
                    #pragma unroll
                    for (int e = 0; e < 4; e++) {
                        bool ok = !diag || (liv[e] < ljv[e]);
                        float d2 = qav[e] + qbv[e] - 2.0f * gv[e];
                        if (ok && d2 < 1.0f) {
                            float d = sqrtf(fmaxf(d2, 0.0f));
                            float h = 1.0f - d;
                            lsum += h * h;
                        }
                    }
                }
            }
        }

        if (havenext) {
            if (newrow) aSt ^= 1;
            bSt ^= 1;
            ti = nti; tj = ntj;
        }
    }

    // per-CTA inter reduction
    #pragma unroll
    for (int o = 16; o > 0; o >>= 1) lsum += __shfl_down_sync(0xffffffffu, lsum, o);
    __syncthreads();   // s_red reuse after gmin scan
    if (lane == 0) s_red[wid] = lsum;
    __syncthreads();
    if (tid == 0) {
        float tsum = 0.0f;
        #pragma unroll
        for (int w = 0; w < 8; w++) tsum += s_red[w];
        g_inter_part[blockIdx.x] = tsum;
    }

    // last-CTA-done finalize
    __threadfence();
    __syncthreads();
    if (tid == 0) {
        unsigned v = atomicAdd(&g_done, 1u);
        s_last = (v == gridDim.x - 1) ? 1u : 0u;
    }
    __syncthreads();
    if (s_last) {
        __threadfence();
        float a = 0.0f, b = 0.0f;
        for (int i = tid; i < GRID_B; i += 256) a += g_inter_part[i];
        for (int i = tid; i < GNUM; i += 256) b += g_intra_part[i];
        #pragma unroll
        for (int o = 16; o > 0; o >>= 1) {
            a += __shfl_down_sync(0xffffffffu, a, o);
            b += __shfl_down_sync(0xffffffffu, b, o);
        }
        __shared__ float fa[8], fb[8];
        if (lane == 0) { fa[wid] = a; fb[wid] = b; }
        __syncthreads();
        if (tid == 0) {
            float A = 0.0f, B = 0.0f;
            #pragma unroll
            for (int w = 0; w < 8; w++) { A += fa[w]; B += fb[w]; }
            out[0] = A / 33550336.0f;              // G*(G-1)/2
            out[1] = B / (float)(GNUM * PNUM);
            g_done = 0;                            // reset for next replay
        }
    }
}

extern "C" void kernel_launch(void* const* d_in, const int* in_sizes, int n_in,
                              void* d_out, int out_size) {
    const float* fea = (const float*)d_in[0];
    float* out = (float*)d_out;

    center_intra_kernel<<<GNUM, 512>>>(fea);

    const int smem_bytes = 4 * 128 * TROW;   // 73728
    cudaFuncSetAttribute(gram_finalize_kernel,
                         cudaFuncAttributeMaxDynamicSharedMemorySize, smem_bytes);
    gram_finalize_kernel<<<GRID_B, 256, smem_bytes>>>(out);
}